// round 1
// baseline (speedup 1.0000x reference)
#include <cuda_runtime.h>
#include <cstdint>

// Problem constants
#define B_    32
#define IC_   16
#define OC_   16
#define KTOT  65536      // (M-1)*(N-1) = 256*256
#define E_    131584     // 2*257*256
#define VOFF  65792      // M*(N-1)
#define KT    32         // k per tile (tiles never cross a 256-wide row)

__device__ __forceinline__ unsigned long long pack2(float lo, float hi) {
    unsigned long long r;
    asm("mov.b64 %0, {%1, %2};" : "=l"(r) : "f"(lo), "f"(hi));
    return r;
}
__device__ __forceinline__ void fma2(unsigned long long &acc,
                                     unsigned long long a, unsigned long long b) {
    asm("fma.rn.f32x2 %0, %1, %2, %0;" : "+l"(acc) : "l"(a), "l"(b));
}
__device__ __forceinline__ float2 unpack2(unsigned long long v) {
    float2 f;
    asm("mov.b64 {%0, %1}, %2;" : "=f"(f.x), "=f"(f.y) : "l"(v));
    return f;
}

// Block: 32 k-lanes (x) x 16 (y).  y = oh*8 + bg:
//   oh in {0,1}   -> which 8 output channels this thread accumulates
//   bg in 0..7    -> which group of 4 batches this thread accumulates
// Block covers: one 32-wide k tile, ALL 32 batches, ALL 16 output channels.
// => every weight element is read from DRAM exactly once across the grid.
__global__ __launch_bounds__(512, 1)
void edges_kernel(const float* __restrict__ x,
                  const float4* __restrict__ w4,     // weight as float4 over t
                  const float* __restrict__ bias,
                  float* __restrict__ out)
{
    __shared__ float4 sw[2][16 * KT];   // [buf][o*32 + klocal] = w[o, ic, k, 0..3]

    const int lane = threadIdx.x;            // k within tile
    const int y    = threadIdx.y;
    const int oh   = y >> 3;                 // o half
    const int bg   = y & 7;                  // batch group
    const int bbase = bg * 4;

    const int k0 = blockIdx.x * KT;
    const int k  = k0 + lane;
    const int i  = k0 >> 8;                  // grid row (constant across tile)
    const int j  = (k0 & 255) + lane;        // grid col, < 256
    const int c0 = k;                        // t=0 gather col
    const int c2 = VOFF + i * 257 + j;       // t=2 gather col (t=3 is c2+1)

    // cooperative weight-slab load assignment: 512 threads x float4 = 8 KB slab
    const int tld  = y * 32 + lane;
    const int o_ld = tld >> 5;
    const int q    = tld & 31;
    // float4 index into weight: (o*16 + ic)*65536 + (k0 + q)
    const int wbase = (o_ld * 16) * 65536 + k0 + q;

    unsigned long long acc[8][4];
    #pragma unroll
    for (int oo = 0; oo < 8; ++oo)
        #pragma unroll
        for (int bb = 0; bb < 4; ++bb)
            acc[oo][bb] = 0ull;

    float4 pre = __ldg(&w4[wbase]);   // ic = 0 slab element
    int buf = 0;

    #pragma unroll 1
    for (int ic = 0; ic < IC_; ++ic) {
        sw[buf][tld] = pre;
        __syncthreads();
        if (ic < IC_ - 1) pre = __ldg(&w4[wbase + (ic + 1) * 65536]);

        // gather x for this thread's 4 batches (all lane-coalesced)
        unsigned long long xA[4], xB[4];
        #pragma unroll
        for (int bb = 0; bb < 4; ++bb) {
            const float* xb = x + ((bbase + bb) * IC_ + ic) * E_;
            float x0 = __ldg(xb + c0);
            float x1 = __ldg(xb + c0 + 256);
            float x2 = __ldg(xb + c2);
            float x3 = __ldg(xb + c2 + 1);
            xA[bb] = pack2(x0, x1);
            xB[bb] = pack2(x2, x3);
        }

        const float4* swrow = &sw[buf][(oh * 8) * KT + lane];
        #pragma unroll
        for (int oo = 0; oo < 8; ++oo) {
            unsigned long long wA, wB;
            unsigned sa = (unsigned)__cvta_generic_to_shared(swrow + oo * KT);
            asm("ld.shared.v2.u64 {%0, %1}, [%2];" : "=l"(wA), "=l"(wB) : "r"(sa));
            #pragma unroll
            for (int bb = 0; bb < 4; ++bb) {
                fma2(acc[oo][bb], wA, xA[bb]);
                fma2(acc[oo][bb], wB, xB[bb]);
            }
        }
        buf ^= 1;
    }

    // epilogue: lo+hi + bias, coalesced STG.32 across lanes
    #pragma unroll
    for (int oo = 0; oo < 8; ++oo) {
        const int o = oh * 8 + oo;
        const float bo = __ldg(&bias[o]);
        #pragma unroll
        for (int bb = 0; bb < 4; ++bb) {
            float2 v = unpack2(acc[oo][bb]);
            out[((bbase + bb) * OC_ + o) * KTOT + k] = v.x + v.y + bo;
        }
    }
}

extern "C" void kernel_launch(void* const* d_in, const int* in_sizes, int n_in,
                              void* d_out, int out_size)
{
    const float*  x    = (const float*)d_in[0];
    const float4* w4   = (const float4*)d_in[1];
    const float*  bias = (const float*)d_in[2];
    float*        out  = (float*)d_out;

    dim3 block(32, 16);
    dim3 grid(KTOT / KT);   // 2048 blocks
    edges_kernel<<<grid, block>>>(x, w4, bias, out);
}

// round 2
// speedup vs baseline: 1.0201x; 1.0201x over previous
#include <cuda_runtime.h>
#include <cstdint>

#define B_    32
#define IC_   16
#define OC_   16
#define KTOT  65536      // (M-1)*(N-1) = 256*256
#define E_    131584     // 2*257*256
#define VOFF  65792      // M*(N-1)
#define KT    32         // k per tile (tiles never cross a 256-wide row)

__device__ __forceinline__ unsigned long long pack2(float lo, float hi) {
    unsigned long long r;
    asm("mov.b64 %0, {%1, %2};" : "=l"(r) : "f"(lo), "f"(hi));
    return r;
}
__device__ __forceinline__ void fma2(unsigned long long &acc,
                                     unsigned long long a, unsigned long long b) {
    asm("fma.rn.f32x2 %0, %1, %2, %0;" : "+l"(acc) : "l"(a), "l"(b));
}
__device__ __forceinline__ float2 unpack2(unsigned long long v) {
    float2 f;
    asm("mov.b64 {%0, %1}, %2;" : "=f"(f.x), "=f"(f.y) : "l"(v));
    return f;
}
__device__ __forceinline__ void cp_async16(unsigned dst, const void* src) {
    asm volatile("cp.async.cg.shared.global [%0], [%1], 16;\n"
                 :: "r"(dst), "l"(src) : "memory");
}
__device__ __forceinline__ void cp_commit() {
    asm volatile("cp.async.commit_group;\n" ::: "memory");
}
__device__ __forceinline__ void cp_wait_all() {
    asm volatile("cp.async.wait_group 0;\n" ::: "memory");
}

// Block: 32 k-lanes (x) x 16 (y).  y = oh*8 + bg.
// Block covers one 32-wide k tile, all 32 batches, all 16 output channels
// => every weight element read from DRAM exactly once.
__global__ __launch_bounds__(512, 1)
void edges_kernel(const float* __restrict__ x,
                  const float4* __restrict__ w4,   // weight viewed as float4 over t
                  const float* __restrict__ bias,
                  float* __restrict__ out)
{
    __shared__ float4 sw[2][16 * KT];   // [buf][o*32 + klocal] = w[o, ic, k, 0..3]

    const int lane = threadIdx.x;
    const int y    = threadIdx.y;
    const int oh   = y >> 3;
    const int bg   = y & 7;
    const int bbase = bg * 4;

    const int k0 = blockIdx.x * KT;
    const int k  = k0 + lane;
    const int i  = k0 >> 8;
    const int j  = (k0 & 255) + lane;
    const int c0 = k;                       // t=0 col; t=1 is c0+256
    const int c2 = VOFF + i * 257 + j;      // t=2 col; t=3 is c2+1

    // cooperative weight-slab copy: 512 threads x 16B = 8 KB slab per ic
    const int tld  = y * 32 + lane;
    const int o_ld = tld >> 5;
    const int q    = tld & 31;
    const float4* wsrc = w4 + (size_t)(o_ld * IC_) * KTOT + k0 + q;  // +ic*KTOT per ic

    unsigned sdst[2];
    sdst[0] = (unsigned)__cvta_generic_to_shared(&sw[0][tld]);
    sdst[1] = (unsigned)__cvta_generic_to_shared(&sw[1][tld]);

    // per-batch x base pointers (advance by E_ per ic)
    const float* xp[4];
    #pragma unroll
    for (int bb = 0; bb < 4; ++bb)
        xp[bb] = x + (size_t)((bbase + bb) * IC_) * E_;

    unsigned long long acc[8][4];
    #pragma unroll
    for (int oo = 0; oo < 8; ++oo)
        #pragma unroll
        for (int bb = 0; bb < 4; ++bb)
            acc[oo][bb] = 0ull;

    float bo[8];
    #pragma unroll
    for (int oo = 0; oo < 8; ++oo) bo[oo] = __ldg(&bias[oh * 8 + oo]);

    // ---- prologue: start weight copy + x gather for ic=0 ----
    cp_async16(sdst[0], wsrc);
    cp_commit();

    float xf[4][4];
    #pragma unroll
    for (int bb = 0; bb < 4; ++bb) {
        const float* xb = xp[bb];
        xf[bb][0] = __ldg(xb + c0);
        xf[bb][1] = __ldg(xb + c0 + 256);
        xf[bb][2] = __ldg(xb + c2);
        xf[bb][3] = __ldg(xb + c2 + 1);
    }

    cp_wait_all();
    __syncthreads();

    int buf = 0;
    #pragma unroll 1
    for (int ic = 0; ic < IC_; ++ic) {
        // start weight copy for ic+1 into the other buffer
        if (ic < IC_ - 1) {
            cp_async16(sdst[buf ^ 1], wsrc + (size_t)(ic + 1) * KTOT);
            cp_commit();
        }

        // pack current x
        unsigned long long xA[4], xB[4];
        #pragma unroll
        for (int bb = 0; bb < 4; ++bb) {
            xA[bb] = pack2(xf[bb][0], xf[bb][1]);
            xB[bb] = pack2(xf[bb][2], xf[bb][3]);
        }

        // prefetch x for ic+1 (hidden under this ic's FMAs)
        if (ic < IC_ - 1) {
            const int off = (ic + 1) * E_;
            #pragma unroll
            for (int bb = 0; bb < 4; ++bb) {
                const float* xb = xp[bb] + off;
                xf[bb][0] = __ldg(xb + c0);
                xf[bb][1] = __ldg(xb + c0 + 256);
                xf[bb][2] = __ldg(xb + c2);
                xf[bb][3] = __ldg(xb + c2 + 1);
            }
        }

        // compute: 8 o x 4 b x 2 fma2
        const float4* swrow = &sw[buf][(oh * 8) * KT + lane];
        #pragma unroll
        for (int oo = 0; oo < 8; ++oo) {
            unsigned long long wA, wB;
            unsigned sa = (unsigned)__cvta_generic_to_shared(swrow + oo * KT);
            asm("ld.shared.v2.u64 {%0, %1}, [%2];" : "=l"(wA), "=l"(wB) : "r"(sa));
            #pragma unroll
            for (int bb = 0; bb < 4; ++bb) {
                fma2(acc[oo][bb], wA, xA[bb]);
                fma2(acc[oo][bb], wB, xB[bb]);
            }
        }

        if (ic < IC_ - 1) {
            cp_wait_all();      // ic+1 slab (issued this iter) must be resident
            __syncthreads();    // and everyone done reading sw[buf]
            buf ^= 1;
        }
    }

    // epilogue: lo+hi + bias, coalesced STG.32 across lanes
    #pragma unroll
    for (int oo = 0; oo < 8; ++oo) {
        const int o = oh * 8 + oo;
        #pragma unroll
        for (int bb = 0; bb < 4; ++bb) {
            float2 v = unpack2(acc[oo][bb]);
            out[(size_t)((bbase + bb) * OC_ + o) * KTOT + k] = v.x + v.y + bo[oo];
        }
    }
}

extern "C" void kernel_launch(void* const* d_in, const int* in_sizes, int n_in,
                              void* d_out, int out_size)
{
    const float*  x    = (const float*)d_in[0];
    const float4* w4   = (const float4*)d_in[1];
    const float*  bias = (const float*)d_in[2];
    float*        out  = (float*)d_out;

    dim3 block(32, 16);
    dim3 grid(KTOT / KT);
    edges_kernel<<<grid, block>>>(x, w4, bias, out);
}